// round 4
// baseline (speedup 1.0000x reference)
#include <cuda_runtime.h>
#include <math.h>

#define Bn 1024
#define Tn 512
#define KK 48
#define NEG (-10000.0f)
#define SSTART 46
#define SSTOP  47
#define BPB 7                 // max batches per block
#define NTHREADS (BPB * KK)   // 336
#define NBLK 148

// Viterbi value history: v entering each step t, per (b, t, s).  ~100 MB scratch.
__device__ float vbuf_g[(size_t)Bn * Tn * KK];

__global__ void __launch_bounds__(NTHREADS, 1)
crf_fused_kernel(const float* __restrict__ feats,
                 const float* __restrict__ trans,
                 const int*   __restrict__ tags,
                 float*       __restrict__ out)
{
    __shared__ float bufE[2][BPB][KK];   // exp(alpha - norm), double buffered
    __shared__ float bufV[2][BPB][KK];   // viterbi v, double buffered
    __shared__ float trM[KK * KK];       // masked transitions
    __shared__ float normU[2][BPB];      // normalizer USED for bufE[q]
    __shared__ float normP[2][BPB];      // published alpha[0] (next normalizer)
    __shared__ float gbuf[BPB][KK];      // gold partials
    __shared__ int   blast[BPB];         // best last tag

    const int tid = threadIdx.x;
    const int bl  = tid / KK;
    const int s   = tid % KK;
    const int blk = blockIdx.x;
    const int cnt   = 6 + (blk < 136);                         // 136*7 + 12*6 = 1024
    const int start = (blk < 136) ? blk * 7 : 136 * 7 + (blk - 136) * 6;
    const int b     = start + bl;
    const bool active = (bl < cnt);

    // Masked transition matrix: trans[next,prev]; row START and col STOP -> NEG
    for (int idx = tid; idx < KK * KK; idx += NTHREADS) {
        int n = idx / KK, p = idx % KK;
        float v = trans[idx];
        if (n == SSTART) v = NEG;
        if (p == SSTOP)  v = NEG;
        trM[idx] = v;
    }
    __syncthreads();

    // Per-thread packed rows: Tpk = trans row (f32x2 pairs), Epk = exp(trans row)
    unsigned long long Tpk[KK / 2], Epk[KK / 2];
#pragma unroll
    for (int i = 0; i < KK / 2; i++) {
        float t0 = trM[s * KK + 2 * i], t1 = trM[s * KK + 2 * i + 1];
        asm("mov.b64 %0, {%1,%2};" : "=l"(Tpk[i]) : "f"(t0), "f"(t1));
        float e0 = __expf(t0), e1 = __expf(t1);   // exp(-10000) -> exactly 0
        asm("mov.b64 %0, {%1,%2};" : "=l"(Epk[i]) : "f"(e0), "f"(e1));
    }
    const float tstop = trM[SSTOP * KK + s];

    // Gold score partials
    const float* fb = feats + (size_t)b * Tn * KK;
    const int*   tb = tags  + (size_t)b * Tn;
    if (active) {
        float gp = 0.0f;
        for (int t = s; t < Tn; t += KK) {
            int tg = tb[t];
            int pv = (t == 0) ? SSTART : tb[t - 1];
            gp += fb[(size_t)t * KK + tg] + trM[tg * KK + pv];
        }
        gbuf[bl][s] = gp;
    }

    // Init buffers (parity 0): alpha_init = NEG except START=0 -> exp: {1,0}; v likewise
    bufE[0][bl][s] = (s == SSTART) ? 1.0f : 0.0f;
    bufV[0][bl][s] = (s == SSTART) ? 0.0f : NEG;
    if (s == 0) { normU[0][bl] = 0.0f; normP[0][bl] = 0.0f; }

    float alpha = 0.0f;
    float v = (s == SSTART) ? 0.0f : NEG;   // ENTRY value for t=0 (stored to vbuf)

    const float* fptr = active ? (fb + s) : (feats + s);   // inactive: harmless reads
    float* vrow = vbuf_g + (size_t)b * Tn * KK + s;

    const unsigned aEb = (unsigned)__cvta_generic_to_shared(&bufE[0][bl][0]);
    const unsigned aVb = (unsigned)__cvta_generic_to_shared(&bufV[0][bl][0]);
    const unsigned bufStride = (unsigned)(sizeof(float) * BPB * KK);

    float femit = fptr[0];

#pragma unroll 1
    for (int t = 0; t < Tn; t++) {
        __syncthreads();
        const int p = t & 1;
        const float M = normU[p][bl];     // normalizer used for bufE[p]
        const float W = normP[p][bl];     // normalizer to use when writing bufE[p^1]
        const float emit = femit;
        const float* np = fptr + KK;
        femit = (t < Tn - 1) ? np[0] : 0.0f;   // prefetch next emit
        fptr = np;

        if (active) vrow[(size_t)t * KK] = v;  // store ENTRY v for backtrace recompute

        const unsigned aE = aEb + (unsigned)p * bufStride;
        const unsigned aV = aVb + (unsigned)p * bufStride;

        unsigned long long acc0 = 0ull, acc1 = 0ull;   // packed fp32 pairs = 0.0f
        float b0 = -INFINITY, b1 = -INFINITY, b2 = -INFINITY, b3 = -INFINITY;
#pragma unroll
        for (int c = 0; c < 12; c++) {
            unsigned long long e01, e23, v01, v23, s01, s23;
            asm volatile("ld.shared.v2.b64 {%0,%1},[%2];"
                         : "=l"(e01), "=l"(e23) : "r"(aE + c * 16));
            asm volatile("ld.shared.v2.b64 {%0,%1},[%2];"
                         : "=l"(v01), "=l"(v23) : "r"(aV + c * 16));
            asm("fma.rn.f32x2 %0,%1,%2,%3;" : "=l"(acc0)
                : "l"(Epk[2 * c]),     "l"(e01), "l"(acc0));
            asm("fma.rn.f32x2 %0,%1,%2,%3;" : "=l"(acc1)
                : "l"(Epk[2 * c + 1]), "l"(e23), "l"(acc1));
            asm("add.rn.f32x2 %0,%1,%2;" : "=l"(s01) : "l"(v01), "l"(Tpk[2 * c]));
            asm("add.rn.f32x2 %0,%1,%2;" : "=l"(s23) : "l"(v23), "l"(Tpk[2 * c + 1]));
            float x0, x1, x2, x3;
            asm("mov.b64 {%0,%1},%2;" : "=f"(x0), "=f"(x1) : "l"(s01));
            asm("mov.b64 {%0,%1},%2;" : "=f"(x2), "=f"(x3) : "l"(s23));
            b0 = fmaxf(b0, x0); b1 = fmaxf(b1, x1);
            b2 = fmaxf(b2, x2); b3 = fmaxf(b3, x3);
        }
        float a0, a1, a2, a3;
        asm("mov.b64 {%0,%1},%2;" : "=f"(a0), "=f"(a1) : "l"(acc0));
        asm("mov.b64 {%0,%1},%2;" : "=f"(a2), "=f"(a3) : "l"(acc1));
        const float ssum = (a0 + a1) + (a2 + a3);
        const float best = fmaxf(fmaxf(b0, b1), fmaxf(b2, b3));  // exact set-max

        alpha = emit + M + __logf(ssum);   // log(0) -> -inf for START row: correct
        v     = best + emit;               // bit-identical value to reference

        const int q = p ^ 1;
        bufE[q][bl][s] = __expf(alpha - W);
        bufV[q][bl][s] = v;
        if (s == 0) { normU[q][bl] = W; normP[q][bl] = alpha; }
    }

    __syncthreads();
    // Terminal terms into buffer 0 (loop done; buffers free)
    bufE[0][bl][s] = alpha + tstop;
    bufV[0][bl][s] = v + tstop;
    __syncthreads();

    if (active && s == 0) {
        float gold = 0.0f;
        for (int i = 0; i < KK; i++) gold += gbuf[bl][i];
        gold += trM[SSTOP * KK + tb[Tn - 1]];

        float mz = -INFINITY;
        for (int i = 0; i < KK; i++) mz = fmaxf(mz, bufE[0][bl][i]);
        float sz = 0.0f;
        for (int i = 0; i < KK; i++) sz += __expf(bufE[0][bl][i] - mz);
        const float logZ = mz + __logf(sz);

        float bv = -INFINITY; int bi = 0;
        for (int i = 0; i < KK; i++) {
            float tv = bufV[0][bl][i];
            if (tv > bv) { bv = tv; bi = i; }   // first-index tie-break
        }
        out[b]      = logZ - gold;   // nll
        out[Bn + b] = bv;            // path_score
        blast[bl]   = bi;
        out[2 * (size_t)Bn + (size_t)b * Tn + (Tn - 1)] = (float)bi;
    }
    __syncthreads();

    // ---- Backtrace: one warp per batch, recompute backpointers from vbuf ----
    const int w = tid >> 5;
    const int lane = tid & 31;
    if (w < cnt) {
        const int bb = start + w;
        const float* vb = vbuf_g + (size_t)bb * Tn * KK;
        float* pout = out + 2 * (size_t)Bn + (size_t)bb * Tn;
        int cur = blast[w];

        // depth-4 prefetch ring over rows t = 511..508
        float ra[4], rb[4];
#pragma unroll
        for (int k = 0; k < 4; k++) {
            int tt = Tn - 1 - k;
            ra[k] = vb[(size_t)tt * KK + lane];
            rb[k] = (lane < 16) ? vb[(size_t)tt * KK + 32 + lane] : -INFINITY;
        }

        int t = Tn - 1;
#pragma unroll 1
        for (int iter = 0; iter < 128; iter++) {
#pragma unroll
            for (int k = 0; k < 4; k++) {
                if (t >= 1) {
                    // bp(t, cur) = first-argmax_prev( v_entry[t][prev] + trM[cur][prev] )
                    float val = ra[k] + trM[cur * KK + lane];
                    int   idx = lane;
                    if (lane < 16) {
                        float vB = rb[k] + trM[cur * KK + 32 + lane];
                        if (vB > val) { val = vB; idx = lane + 32; }  // tie -> lower idx
                    }
#pragma unroll
                    for (int off = 16; off >= 1; off >>= 1) {
                        float ov = __shfl_xor_sync(0xffffffffu, val, off);
                        int   oi = __shfl_xor_sync(0xffffffffu, idx, off);
                        if (ov > val || (ov == val && oi < idx)) { val = ov; idx = oi; }
                    }
                    cur = idx;
                    if (lane == 0) pout[t - 1] = (float)cur;

                    const int tn = t - 4;            // refill this ring slot
                    if (tn >= 1) {
                        ra[k] = vb[(size_t)tn * KK + lane];
                        if (lane < 16) rb[k] = vb[(size_t)tn * KK + 32 + lane];
                    }
                    t--;
                }
            }
        }
    }
}

extern "C" void kernel_launch(void* const* d_in, const int* in_sizes, int n_in,
                              void* d_out, int out_size)
{
    const float* feats = (const float*)d_in[0];
    const float* trans = (const float*)d_in[1];
    const int*   tags  = (const int*)d_in[2];
    float* out = (float*)d_out;

    crf_fused_kernel<<<NBLK, NTHREADS>>>(feats, trans, tags, out);
}